// round 5
// baseline (speedup 1.0000x reference)
#include <cuda_runtime.h>
#include <math.h>

#define C_SIZE 1000
#define TAIL_LANES 26       // chunks 224..249 handled by lanes 0..25 in group j=7

// Device-global scratch (no allocations allowed)
__device__ float g_conf[C_SIZE];
__device__ int   g_counts[C_SIZE];

// ---------------------------------------------------------------------------
// Zero the accumulators (must run every launch: graph replays reuse them)
// ---------------------------------------------------------------------------
__global__ void mdca_zero_kernel() {
    int i = blockIdx.x * blockDim.x + threadIdx.x;
    if (i < C_SIZE) {
        g_conf[i]   = 0.0f;
        g_counts[i] = 0;
    }
}

// ---------------------------------------------------------------------------
// Bincount of targets (int32 input — JAX x64-disabled downcasts int64->int32;
// index clamped so a bad value can never fault)
// ---------------------------------------------------------------------------
__global__ void mdca_counts_kernel(const int* __restrict__ tgt, int B) {
    int i = blockIdx.x * blockDim.x + threadIdx.x;
    if (i < B) {
        int c = tgt[i];
        c = (c < 0) ? 0 : ((c >= C_SIZE) ? (C_SIZE - 1) : c);
        atomicAdd(&g_counts[c], 1);
    }
}

// ---------------------------------------------------------------------------
// Main single-pass kernel: one warp per row.
//   norm = sqrt(sum x^2) + eps ; p = softmax(x / norm) ; g_conf[c] += p[c]
// Each lane owns float4 chunks {lane + 32j : j=0..6} and (if lane<26) 224+lane.
// Per-lane register accumulators cover the same 32 class-groups across all
// rows the warp visits, so accumulation is register-resident; one RED flush.
// ---------------------------------------------------------------------------
__global__ __launch_bounds__(128, 5)
void mdca_main_kernel(const float* __restrict__ out, int B) {
    const int lane   = threadIdx.x & 31;
    const int warp   = (blockIdx.x * blockDim.x + threadIdx.x) >> 5;
    const int nwarps = (gridDim.x * blockDim.x) >> 5;
    const bool tail_ok = (lane < TAIL_LANES);

    float4 acc[8];
    #pragma unroll
    for (int j = 0; j < 8; j++) acc[j] = make_float4(0.f, 0.f, 0.f, 0.f);

    const float LOG2E = 1.4426950408889634f;

    for (int row = warp; row < B; row += nwarps) {
        const float4* __restrict__ rp =
            (const float4*)(out + (size_t)row * C_SIZE);

        // ---- load row (8 x LDG.128 per lane, fully coalesced) ----
        float4 v[8];
        #pragma unroll
        for (int j = 0; j < 7; j++) v[j] = rp[lane + 32 * j];
        v[7] = tail_ok ? rp[224 + lane] : make_float4(0.f, 0.f, 0.f, 0.f);

        // ---- sum of squares + max, fused pass ----
        float ss = 0.0f;
        float m  = -3.0e38f;
        #pragma unroll
        for (int j = 0; j < 7; j++) {
            float4 w = v[j];
            ss = fmaf(w.x, w.x, ss); ss = fmaf(w.y, w.y, ss);
            ss = fmaf(w.z, w.z, ss); ss = fmaf(w.w, w.w, ss);
            m = fmaxf(m, fmaxf(fmaxf(w.x, w.y), fmaxf(w.z, w.w)));
        }
        {
            float4 w = v[7];            // zeros when !tail_ok -> ss unaffected
            ss = fmaf(w.x, w.x, ss); ss = fmaf(w.y, w.y, ss);
            ss = fmaf(w.z, w.z, ss); ss = fmaf(w.w, w.w, ss);
            if (tail_ok)
                m = fmaxf(m, fmaxf(fmaxf(w.x, w.y), fmaxf(w.z, w.w)));
        }
        #pragma unroll
        for (int o = 16; o > 0; o >>= 1) {
            ss += __shfl_xor_sync(0xffffffffu, ss, o);
            m   = fmaxf(m, __shfl_xor_sync(0xffffffffu, m, o));
        }

        const float inv = 1.0f / (sqrtf(ss) + 1e-7f);
        // exp((x - m) * inv) = exp2(x * a + b)
        const float a = inv * LOG2E;
        const float b = -m * inv * LOG2E;

        // ---- exponentials + sum (in place: v[j] becomes exp terms) ----
        float se = 0.0f;
        #pragma unroll
        for (int j = 0; j < 7; j++) {
            float4 w = v[j];
            float4 e;
            e.x = exp2f(fmaf(w.x, a, b));
            e.y = exp2f(fmaf(w.y, a, b));
            e.z = exp2f(fmaf(w.z, a, b));
            e.w = exp2f(fmaf(w.w, a, b));
            se += (e.x + e.y) + (e.z + e.w);
            v[j] = e;
        }
        {
            float4 e = make_float4(0.f, 0.f, 0.f, 0.f);
            if (tail_ok) {
                float4 w = v[7];
                e.x = exp2f(fmaf(w.x, a, b));
                e.y = exp2f(fmaf(w.y, a, b));
                e.z = exp2f(fmaf(w.z, a, b));
                e.w = exp2f(fmaf(w.w, a, b));
                se += (e.x + e.y) + (e.z + e.w);
            }
            v[7] = e;
        }
        #pragma unroll
        for (int o = 16; o > 0; o >>= 1)
            se += __shfl_xor_sync(0xffffffffu, se, o);

        const float rs = 1.0f / se;

        // ---- accumulate probabilities ----
        #pragma unroll
        for (int j = 0; j < 8; j++) {
            acc[j].x = fmaf(v[j].x, rs, acc[j].x);
            acc[j].y = fmaf(v[j].y, rs, acc[j].y);
            acc[j].z = fmaf(v[j].z, rs, acc[j].z);
            acc[j].w = fmaf(v[j].w, rs, acc[j].w);
        }
    }

    // ---- flush per-warp partials: warp-wide REDs to g_conf ----
    #pragma unroll
    for (int j = 0; j < 8; j++) {
        int chunk = (j < 7) ? (32 * j + lane) : (224 + lane);
        if (j < 7 || tail_ok) {
            atomicAdd(&g_conf[4 * chunk + 0], acc[j].x);
            atomicAdd(&g_conf[4 * chunk + 1], acc[j].y);
            atomicAdd(&g_conf[4 * chunk + 2], acc[j].z);
            atomicAdd(&g_conf[4 * chunk + 3], acc[j].w);
        }
    }
}

// ---------------------------------------------------------------------------
// Final reduction: mean_c |conf[c]/B - counts[c]/B| -> scalar
// ---------------------------------------------------------------------------
__global__ void mdca_final_kernel(float* __restrict__ outp, int B) {
    __shared__ float sh[32];
    int t = threadIdx.x;
    float d = 0.0f;
    if (t < C_SIZE)
        d = fabsf(g_conf[t] - (float)g_counts[t]);
    #pragma unroll
    for (int o = 16; o > 0; o >>= 1)
        d += __shfl_xor_sync(0xffffffffu, d, o);
    if ((t & 31) == 0) sh[t >> 5] = d;
    __syncthreads();
    if (t < 32) {
        float v = sh[t];   // blockDim.x == 1024 -> exactly 32 warps
        #pragma unroll
        for (int o = 16; o > 0; o >>= 1)
            v += __shfl_xor_sync(0xffffffffu, v, o);
        if (t == 0)
            outp[0] = v / ((float)B * (float)C_SIZE);
    }
}

// ---------------------------------------------------------------------------
extern "C" void kernel_launch(void* const* d_in, const int* in_sizes, int n_in,
                              void* d_out, int out_size) {
    // Robust input resolution: the [B, 1000] fp32 logits tensor is the larger
    // input; the target vector is the smaller one.
    int io = 0, it = 1;
    if (n_in >= 2 && in_sizes[1] > in_sizes[0]) { io = 1; it = 0; }

    const float* outp = (const float*)d_in[io];   // [B, 1000] fp32
    const int*   tgt  = (const int*)d_in[it];     // [B] int32
    float* res = (float*)d_out;

    const int B = in_sizes[it];

    mdca_zero_kernel<<<(C_SIZE + 255) / 256, 256>>>();
    mdca_counts_kernel<<<(B + 255) / 256, 256>>>(tgt, B);
    mdca_main_kernel<<<740, 128>>>(outp, B);
    mdca_final_kernel<<<1, 1024>>>(res, B);
}

// round 6
// speedup vs baseline: 1.4909x; 1.4909x over previous
#include <cuda_runtime.h>
#include <math.h>

#define C_SIZE 1000
#define NCHUNK 250          // float4 chunks per row
#define GRID_BLKS 1480      // 148 SMs x 10 CTAs -> exactly one wave

// Device-global scratch (no allocations allowed).
// INVARIANT: all three are zero at kernel entry; the last-finishing block
// re-zeroes them on the way out, so graph replays stay correct.
__device__ float g_conf[C_SIZE];
__device__ int   g_counts[C_SIZE];
__device__ int   g_done;

__global__ __launch_bounds__(128, 10)
void mdca_fused_kernel(const float* __restrict__ logits,
                       const int*   __restrict__ tgt,
                       int B, float* __restrict__ res) {
    __shared__ float sh_ss[4];
    __shared__ float sh_se[4];
    __shared__ float sh_fin[4];
    __shared__ int   sh_last;

    const int t    = threadIdx.x;
    const int lane = t & 31;
    const int wid  = t >> 5;

    // ---------------- phase 0: target bincount (grid-strided) -------------
    for (int i = blockIdx.x * 128 + t; i < B; i += (int)gridDim.x * 128) {
        int c = tgt[i];
        c = (c < 0) ? 0 : ((c >= C_SIZE) ? C_SIZE - 1 : c);
        atomicAdd(&g_counts[c], 1);
    }

    // ---------------- phase 1: per-row L2-norm softmax, conf accum --------
    // Thread t owns float4 chunks k0 = t and k1 = 128+t (k1 valid if < 250),
    // i.e. classes [4t,4t+3] and [512+4t, 512+4t+3]. Coalesced LDG.128.
    const int  k1   = 128 + t;
    const bool has1 = (k1 < NCHUNK);

    float4 acc0 = make_float4(0.f, 0.f, 0.f, 0.f);
    float4 acc1 = make_float4(0.f, 0.f, 0.f, 0.f);
    const float LOG2E = 1.4426950408889634f;

    for (int row = blockIdx.x; row < B; row += (int)gridDim.x) {
        const float4* __restrict__ rp =
            (const float4*)(logits + (size_t)row * C_SIZE);

        float4 v0 = rp[t];
        float4 v1 = make_float4(0.f, 0.f, 0.f, 0.f);
        if (has1) v1 = rp[k1];

        // sum of squares (v1 zeros contribute nothing)
        float ss;
        ss = v0.x * v0.x;
        ss = fmaf(v0.y, v0.y, ss); ss = fmaf(v0.z, v0.z, ss);
        ss = fmaf(v0.w, v0.w, ss);
        ss = fmaf(v1.x, v1.x, ss); ss = fmaf(v1.y, v1.y, ss);
        ss = fmaf(v1.z, v1.z, ss); ss = fmaf(v1.w, v1.w, ss);

        #pragma unroll
        for (int o = 16; o > 0; o >>= 1)
            ss += __shfl_xor_sync(0xffffffffu, ss, o);
        if (lane == 0) sh_ss[wid] = ss;
        __syncthreads();                                   // sync 1
        ss = (sh_ss[0] + sh_ss[1]) + (sh_ss[2] + sh_ss[3]);

        // 1/(sqrt(ss)+1e-7) == rsqrt(ss) to fp32 precision (norm ~31.6)
        const float a = LOG2E * rsqrtf(ss);

        // exponentials; no max-shift needed (|x/norm| << 1)
        float4 e0, e1;
        e0.x = exp2f(v0.x * a); e0.y = exp2f(v0.y * a);
        e0.z = exp2f(v0.z * a); e0.w = exp2f(v0.w * a);
        float se = (e0.x + e0.y) + (e0.z + e0.w);
        e1 = make_float4(0.f, 0.f, 0.f, 0.f);
        if (has1) {
            e1.x = exp2f(v1.x * a); e1.y = exp2f(v1.y * a);
            e1.z = exp2f(v1.z * a); e1.w = exp2f(v1.w * a);
            se += (e1.x + e1.y) + (e1.z + e1.w);
        }

        #pragma unroll
        for (int o = 16; o > 0; o >>= 1)
            se += __shfl_xor_sync(0xffffffffu, se, o);
        if (lane == 0) sh_se[wid] = se;
        __syncthreads();                                   // sync 2
        se = (sh_se[0] + sh_se[1]) + (sh_se[2] + sh_se[3]);

        const float rs = __fdividef(1.0f, se);

        acc0.x = fmaf(e0.x, rs, acc0.x); acc0.y = fmaf(e0.y, rs, acc0.y);
        acc0.z = fmaf(e0.z, rs, acc0.z); acc0.w = fmaf(e0.w, rs, acc0.w);
        acc1.x = fmaf(e1.x, rs, acc1.x); acc1.y = fmaf(e1.y, rs, acc1.y);
        acc1.z = fmaf(e1.z, rs, acc1.z); acc1.w = fmaf(e1.w, rs, acc1.w);
    }

    // ---------------- phase 2: flush per-block partials --------------------
    {
        const int c0 = 4 * t;
        atomicAdd(&g_conf[c0 + 0], acc0.x);
        atomicAdd(&g_conf[c0 + 1], acc0.y);
        atomicAdd(&g_conf[c0 + 2], acc0.z);
        atomicAdd(&g_conf[c0 + 3], acc0.w);
        if (has1) {
            const int c1 = 4 * k1;
            atomicAdd(&g_conf[c1 + 0], acc1.x);
            atomicAdd(&g_conf[c1 + 1], acc1.y);
            atomicAdd(&g_conf[c1 + 2], acc1.z);
            atomicAdd(&g_conf[c1 + 3], acc1.w);
        }
    }
    __threadfence();
    __syncthreads();

    // ---------------- phase 3: last block computes the scalar --------------
    if (t == 0)
        sh_last = (atomicAdd(&g_done, 1) == (int)gridDim.x - 1) ? 1 : 0;
    __syncthreads();
    if (!sh_last) return;

    // atomicExch reads the final value AND re-zeroes for the next replay.
    float d = 0.0f;
    #pragma unroll
    for (int j = 0; j < 8; j++) {
        int c = t + 128 * j;
        if (c < C_SIZE) {
            float cf = atomicExch(&g_conf[c], 0.0f);
            int   ct = atomicExch(&g_counts[c], 0);
            d += fabsf(cf - (float)ct);
        }
    }
    #pragma unroll
    for (int o = 16; o > 0; o >>= 1)
        d += __shfl_xor_sync(0xffffffffu, d, o);
    if (lane == 0) sh_fin[wid] = d;
    __syncthreads();
    if (t == 0) {
        float tot = (sh_fin[0] + sh_fin[1]) + (sh_fin[2] + sh_fin[3]);
        res[0] = tot / ((float)B * (float)C_SIZE);
        g_done = 0;                       // reset for next graph replay
        __threadfence();
    }
}

// ---------------------------------------------------------------------------
extern "C" void kernel_launch(void* const* d_in, const int* in_sizes, int n_in,
                              void* d_out, int out_size) {
    // Robust input resolution: the [B,1000] fp32 logits tensor is the larger
    // input; the target vector is the smaller one.
    int io = 0, it = 1;
    if (n_in >= 2 && in_sizes[1] > in_sizes[0]) { io = 1; it = 0; }

    const float* logits = (const float*)d_in[io];  // [B, 1000] fp32
    const int*   tgt    = (const int*)d_in[it];    // [B] int32
    float* res = (float*)d_out;

    const int B = in_sizes[it];

    mdca_fused_kernel<<<GRID_BLKS, 128>>>(logits, tgt, B, res);
}

// round 10
// speedup vs baseline: 1.8601x; 1.2476x over previous
#include <cuda_runtime.h>
#include <math.h>

#define C_SIZE 1000
#define NCHUNK 250          // float4 chunks per row
#define ROWS   4            // rows per loop iteration
#define GRID_BLKS 1184      // 148 SMs x 8 CTAs -> exactly one wave

// Device-global scratch (no allocations allowed).
// INVARIANT: zero at kernel entry; the last-finishing block re-zeroes on the
// way out, so graph replays stay correct.
__device__ float g_conf[C_SIZE];
__device__ int   g_counts[C_SIZE];
__device__ int   g_done;

__global__ __launch_bounds__(128, 8)
void mdca_fused_kernel(const float* __restrict__ logits,
                       const int*   __restrict__ tgt,
                       int B, float* __restrict__ res) {
    __shared__ float sh_ss[ROWS][4];
    __shared__ float sh_se[ROWS][4];
    __shared__ float sh_fin[4];
    __shared__ int   sh_last;

    const int t    = threadIdx.x;
    const int lane = t & 31;
    const int wid  = t >> 5;

    // ---------------- phase 0: target bincount (grid-strided) -------------
    for (int i = blockIdx.x * 128 + t; i < B; i += (int)gridDim.x * 128) {
        int c = tgt[i];
        c = (c < 0) ? 0 : ((c >= C_SIZE) ? C_SIZE - 1 : c);
        atomicAdd(&g_counts[c], 1);
    }

    // ---------------- phase 1: 4 rows per iteration ------------------------
    // Thread t owns float4 chunks t and 128+t (i.e. classes [4t,4t+3] and
    // [512+4t,512+4t+3]) in every row -> register-resident class accumulators.
    const int   k1    = 128 + t;
    const bool  has1  = (k1 < NCHUNK);
    const float mask1 = has1 ? 1.0f : 0.0f;   // kills exp2(0)=1 on tail threads

    float4 acc0 = make_float4(0.f, 0.f, 0.f, 0.f);
    float4 acc1 = make_float4(0.f, 0.f, 0.f, 0.f);
    const float LOG2E = 1.4426950408889634f;

    for (int row0 = blockIdx.x * ROWS; row0 < B;
         row0 += (int)gridDim.x * ROWS) {

        // ---- front-batched loads: 8 independent LDG.128 per thread ----
        float4 v[2 * ROWS];
        #pragma unroll
        for (int r = 0; r < ROWS; r++) {
            const int row = row0 + r;
            const bool ok = (row < B);
            const float4* __restrict__ rp =
                (const float4*)(logits + (size_t)row * C_SIZE);
            v[2 * r]     = ok ? rp[t]
                              : make_float4(0.f, 0.f, 0.f, 0.f);
            v[2 * r + 1] = (ok && has1) ? rp[k1]
                              : make_float4(0.f, 0.f, 0.f, 0.f);
        }

        // ---- sum of squares per row ----
        float ss[ROWS];
        #pragma unroll
        for (int r = 0; r < ROWS; r++) {
            float4 w0 = v[2 * r], w1 = v[2 * r + 1];
            float s;
            s = w0.x * w0.x;
            s = fmaf(w0.y, w0.y, s); s = fmaf(w0.z, w0.z, s);
            s = fmaf(w0.w, w0.w, s);
            s = fmaf(w1.x, w1.x, s); s = fmaf(w1.y, w1.y, s);
            s = fmaf(w1.z, w1.z, s); s = fmaf(w1.w, w1.w, s);
            ss[r] = s;
        }
        // interleaved warp reductions (4 independent chains)
        #pragma unroll
        for (int o = 16; o > 0; o >>= 1) {
            #pragma unroll
            for (int r = 0; r < ROWS; r++)
                ss[r] += __shfl_xor_sync(0xffffffffu, ss[r], o);
        }
        if (lane == 0) {
            #pragma unroll
            for (int r = 0; r < ROWS; r++) sh_ss[r][wid] = ss[r];
        }
        __syncthreads();                                   // barrier 1

        // ---- exponentials in place + per-row sums ----
        float se[ROWS];
        #pragma unroll
        for (int r = 0; r < ROWS; r++) {
            float s = (sh_ss[r][0] + sh_ss[r][1]) +
                      (sh_ss[r][2] + sh_ss[r][3]);
            // 1/(sqrt+1e-7) == rsqrt to fp32 precision (norm ~ 31.6);
            // fmax guard keeps padded rows finite.
            const float a = LOG2E * rsqrtf(fmaxf(s, 1e-30f));
            float4 w0 = v[2 * r], w1 = v[2 * r + 1];
            float4 e0, e1;
            e0.x = exp2f(w0.x * a); e0.y = exp2f(w0.y * a);
            e0.z = exp2f(w0.z * a); e0.w = exp2f(w0.w * a);
            // mask1 zeroes the 6 tail threads whose chunk-1 doesn't exist
            // (exp2(0)=1 would otherwise add 24 spurious units to se).
            e1.x = mask1 * exp2f(w1.x * a); e1.y = mask1 * exp2f(w1.y * a);
            e1.z = mask1 * exp2f(w1.z * a); e1.w = mask1 * exp2f(w1.w * a);
            v[2 * r] = e0; v[2 * r + 1] = e1;
            se[r] = ((e0.x + e0.y) + (e0.z + e0.w)) +
                    ((e1.x + e1.y) + (e1.z + e1.w));
        }
        #pragma unroll
        for (int o = 16; o > 0; o >>= 1) {
            #pragma unroll
            for (int r = 0; r < ROWS; r++)
                se[r] += __shfl_xor_sync(0xffffffffu, se[r], o);
        }
        if (lane == 0) {
            #pragma unroll
            for (int r = 0; r < ROWS; r++) sh_se[r][wid] = se[r];
        }
        __syncthreads();                                   // barrier 2

        // ---- accumulate probabilities ----
        #pragma unroll
        for (int r = 0; r < ROWS; r++) {
            float s = (sh_se[r][0] + sh_se[r][1]) +
                      (sh_se[r][2] + sh_se[r][3]);
            const float rs = (row0 + r < B) ? __fdividef(1.0f, s) : 0.0f;
            float4 e0 = v[2 * r], e1 = v[2 * r + 1];
            acc0.x = fmaf(e0.x, rs, acc0.x); acc0.y = fmaf(e0.y, rs, acc0.y);
            acc0.z = fmaf(e0.z, rs, acc0.z); acc0.w = fmaf(e0.w, rs, acc0.w);
            acc1.x = fmaf(e1.x, rs, acc1.x); acc1.y = fmaf(e1.y, rs, acc1.y);
            acc1.z = fmaf(e1.z, rs, acc1.z); acc1.w = fmaf(e1.w, rs, acc1.w);
        }
    }

    // ---------------- phase 2: flush per-block partials --------------------
    {
        const int c0 = 4 * t;
        atomicAdd(&g_conf[c0 + 0], acc0.x);
        atomicAdd(&g_conf[c0 + 1], acc0.y);
        atomicAdd(&g_conf[c0 + 2], acc0.z);
        atomicAdd(&g_conf[c0 + 3], acc0.w);
        if (has1) {
            const int c1 = 4 * k1;
            atomicAdd(&g_conf[c1 + 0], acc1.x);
            atomicAdd(&g_conf[c1 + 1], acc1.y);
            atomicAdd(&g_conf[c1 + 2], acc1.z);
            atomicAdd(&g_conf[c1 + 3], acc1.w);
        }
    }
    __threadfence();
    __syncthreads();

    // ---------------- phase 3: last block computes the scalar --------------
    if (t == 0)
        sh_last = (atomicAdd(&g_done, 1) == (int)gridDim.x - 1) ? 1 : 0;
    __syncthreads();
    if (!sh_last) return;

    // atomicExch reads the final value AND re-zeroes for the next replay.
    float d = 0.0f;
    #pragma unroll
    for (int j = 0; j < 8; j++) {
        int c = t + 128 * j;
        if (c < C_SIZE) {
            float cf = atomicExch(&g_conf[c], 0.0f);
            int   ct = atomicExch(&g_counts[c], 0);
            d += fabsf(cf - (float)ct);
        }
    }
    #pragma unroll
    for (int o = 16; o > 0; o >>= 1)
        d += __shfl_xor_sync(0xffffffffu, d, o);
    if (lane == 0) sh_fin[wid] = d;
    __syncthreads();
    if (t == 0) {
        float tot = (sh_fin[0] + sh_fin[1]) + (sh_fin[2] + sh_fin[3]);
        res[0] = tot / ((float)B * (float)C_SIZE);
        g_done = 0;                       // reset for next graph replay
        __threadfence();
    }
}

// ---------------------------------------------------------------------------
extern "C" void kernel_launch(void* const* d_in, const int* in_sizes, int n_in,
                              void* d_out, int out_size) {
    // Robust input resolution: the [B,1000] fp32 logits tensor is the larger
    // input; the target vector is the smaller one.
    int io = 0, it = 1;
    if (n_in >= 2 && in_sizes[1] > in_sizes[0]) { io = 1; it = 0; }

    const float* logits = (const float*)d_in[io];  // [B, 1000] fp32
    const int*   tgt    = (const int*)d_in[it];    // [B] int32
    float* res = (float*)d_out;

    const int B = in_sizes[it];

    mdca_fused_kernel<<<GRID_BLKS, 128>>>(logits, tgt, B, res);
}